// round 6
// baseline (speedup 1.0000x reference)
#include <cuda_runtime.h>
#include <cstdint>
#include <cstddef>

// Correlation: out[b, ix*21+iy, h, w] = sum_c f1[b,c,h,w] * f2[b,c,h+2ix-20, w+2iy-20]
// B=4, C=128, H=96, W=192, D=20, stride 2 -> 441 offsets.
//
// Parity trick (R2, proven): stride-2 correlation becomes a dense 21-tap FIR on
// parity-compressed index u (w = 2u+p): out[u][j] += f1[u] * f2p[u + j - 10].
// This round: occupancy play. Tap dim split in two halves (jh) -> 44 accs/thread,
// 672 threads/CTA, <=96 regs (launch_bounds) -> 21 warps/SM instead of 10.5.
// Scalar FFMA (FFMA2 shown pipe-neutral in R4). LDG->reg->STS staging, CC=2.

#define CC        2                    // channels per smem chunk
#define NTHR      672                  // 7 q * 2 p * 2 jh * 24 t
#define S1_FLOATS (CC * 2 * 96)        // [c][parity][96]
#define S2_FLOATS (CC * 7 * 2 * 120)   // [c][q][parity][120] (116 used, pad 120)
#define BUF_FLOATS (S1_FLOATS + S2_FLOATS)   // 3744 floats
#define S2OFF     S1_FLOATS
#define TOTAL_F2  (CC * 96 + CC * 7 * 120)   // 1872 float2 loads per chunk
#define NL        3                    // ceil(1872/672)

__global__ void __launch_bounds__(NTHR)
corr_kernel(const float* __restrict__ f1, const float* __restrict__ f2,
            float* __restrict__ out)
{
    extern __shared__ float smem[];

    const int h   = blockIdx.x;   // 0..95
    const int b   = blockIdx.y;   // 0..3
    const int ixg = blockIdx.z;   // 0..2
    const int tid = threadIdx.x;

    const int q   = tid / 96;          // 0..6 : ix within group
    const int r0  = tid % 96;
    const int p   = r0 / 48;           // parity of w
    const int r1  = r0 % 48;
    const int jh  = r1 / 24;           // tap half: j = 10*jh + jj, jj 0..10
    const int t   = r1 % 24;           // u-tile
    const int u0  = 4 * t;             // first parity-index owned
    const int ix     = ixg * 7 + q;
    const int h2base = h + 14 * ixg - 20;

    float acc[44];                     // [k 0..3][jj 0..10]
    #pragma unroll
    for (int i = 0; i < 44; i++) acc[i] = 0.0f;

    float2 v[NL];                      // register prefetch slots

    auto load_chunk = [&](int c0) {
        #pragma unroll
        for (int i = 0; i < NL; i++) {
            int idx = tid + i * NTHR;
            float2 val = make_float2(0.0f, 0.0f);
            if (idx < TOTAL_F2) {
                if (idx < CC * 96) {
                    int c = idx / 96;
                    int u = idx - c * 96;
                    val = *reinterpret_cast<const float2*>(
                        f1 + (((size_t)(b * 128 + c0 + c)) * 96 + h) * 192 + 2 * u);
                } else {
                    int t2 = idx - CC * 96;
                    int c  = t2 / 840;
                    int rr = t2 - c * 840;
                    int qq = rr / 120;
                    int s  = rr - qq * 120;
                    int h2 = h2base + 2 * qq;
                    int w0 = 2 * s - 20;
                    if (s < 116 && (unsigned)h2 < 96u && (unsigned)w0 < 192u)
                        val = *reinterpret_cast<const float2*>(
                            f2 + (((size_t)(b * 128 + c0 + c)) * 96 + h2) * 192 + w0);
                }
            }
            v[i] = val;
        }
    };

    auto store_chunk = [&](float* buf) {
        #pragma unroll
        for (int i = 0; i < NL; i++) {
            int idx = tid + i * NTHR;
            if (idx < TOTAL_F2) {
                if (idx < CC * 96) {
                    int c = idx / 96;
                    int u = idx - c * 96;
                    buf[(c * 2 + 0) * 96 + u] = v[i].x;   // even parity
                    buf[(c * 2 + 1) * 96 + u] = v[i].y;   // odd parity
                } else {
                    int t2 = idx - CC * 96;
                    int c  = t2 / 840;
                    int rr = t2 - c * 840;
                    int qq = rr / 120;
                    int s  = rr - qq * 120;
                    float* base = buf + S2OFF + ((c * 7 + qq) * 2) * 120 + s;
                    base[0]   = v[i].x;   // even parity
                    base[120] = v[i].y;   // odd parity
                }
            }
        }
    };

    // prologue
    load_chunk(0);
    store_chunk(smem);
    __syncthreads();

    const int NCHUNK = 128 / CC;   // 64
    #pragma unroll 1
    for (int cc = 0; cc < NCHUNK; cc++) {
        const float* cur = smem + (cc & 1) * BUF_FLOATS;
        float*       nxt = smem + ((cc + 1) & 1) * BUF_FLOATS;

        if (cc + 1 < NCHUNK) load_chunk((cc + 1) * CC);   // LDGs in flight

        #pragma unroll
        for (int c = 0; c < CC; c++) {
            float4 v1 = *reinterpret_cast<const float4*>(cur + (c * 2 + p) * 96 + u0);
            // window slots needed: u0 + 10*jh + jj + k  (jj 0..10, k 0..3)
            // aligned base a0 = u0 + 8*jh -> rel index = 2*jh + k + jj in [0,15]
            const float4* wp = reinterpret_cast<const float4*>(
                cur + S2OFF + ((c * 7 + q) * 2 + p) * 120 + u0 + 8 * jh);
            float4 W0 = wp[0], W1 = wp[1], W2 = wp[2], W3 = wp[3];
            float w[16] = {W0.x, W0.y, W0.z, W0.w, W1.x, W1.y, W1.z, W1.w,
                           W2.x, W2.y, W2.z, W2.w, W3.x, W3.y, W3.z, W3.w};
            float a[4] = {v1.x, v1.y, v1.z, v1.w};
            #pragma unroll
            for (int k = 0; k < 4; k++) {
                float fv = a[k];
                int base = 2 * jh + k;
                #pragma unroll
                for (int jj = 0; jj < 11; jj++)
                    acc[k * 11 + jj] = fmaf(fv, w[base + jj], acc[k * 11 + jj]);
            }
        }

        if (cc + 1 < NCHUNK) store_chunk(nxt);
        __syncthreads();
    }

    // store: j = 10*jh + jj (j=10 written identically by both halves)
    const int wbase = 2 * u0 + p;
    size_t obase = (((size_t)b * 441 + (size_t)ix * 21 + 10 * jh) * 96 + h) * 192;
    #pragma unroll
    for (int jj = 0; jj < 11; jj++) {
        size_t ob = obase + (size_t)jj * (96 * 192) + wbase;
        #pragma unroll
        for (int k = 0; k < 4; k++)
            out[ob + 2 * k] = acc[k * 11 + jj];
    }
}

extern "C" void kernel_launch(void* const* d_in, const int* in_sizes, int n_in,
                              void* d_out, int out_size)
{
    const float* f1 = (const float*)d_in[0];
    const float* f2 = (const float*)d_in[1];
    float* out = (float*)d_out;

    size_t smem_bytes = (size_t)2 * BUF_FLOATS * sizeof(float);   // 29952 B
    cudaFuncSetAttribute(corr_kernel, cudaFuncAttributeMaxDynamicSharedMemorySize,
                         (int)smem_bytes);

    dim3 grid(96, 4, 3);   // (h, b, ix-group)
    corr_kernel<<<grid, NTHR, smem_bytes>>>(f1, f2, out);
}

// round 7
// speedup vs baseline: 2.1979x; 2.1979x over previous
#include <cuda_runtime.h>
#include <cstdint>
#include <cstddef>

// Correlation: out[b, ix*21+iy, h, w] = sum_c f1[b,c,h,w] * f2[b,c,h+2ix-20, w+2iy-20]
// B=4, C=128, H=96, W=192, D=20, stride 2 -> 441 offsets.
//
// Parity FIR: out[u][j] += f1[u] * f2p[u+j-10]; smem slot s = u + j (s<116 valid,
// 116..119 zeroed). Tap split j = 12*jh + jj: 12 % 4 == 0 keeps the window base
// u0 + 12*jh float4-aligned, so ALL register-array indices are compile-time
// (R6's dynamic w[2*jh+k+jj] caused a 43% ALU-pipe disaster). jh=1 computes 3
// garbage taps (j>20) from zero-padded slots; never stored.
// 672 threads (7q x 2jh x 2p x 24t), 48 accs, CC=2, double-buffered staging.

#define CC        2                    // channels per smem chunk
#define NTHR      672
#define S1_FLOATS (CC * 2 * 96)        // [c][parity][96]
#define S2_FLOATS (CC * 7 * 2 * 120)   // [c][q][parity][120] (116 valid + 4 zero)
#define BUF_FLOATS (S1_FLOATS + S2_FLOATS)   // 3744 floats
#define S2OFF     S1_FLOATS
#define TOTAL_F2  (CC * 96 + CC * 7 * 120)   // 1872 float2 loads per chunk
#define NL        3                    // ceil(1872/672)

__global__ void __launch_bounds__(NTHR, 1)
corr_kernel(const float* __restrict__ f1, const float* __restrict__ f2,
            float* __restrict__ out)
{
    extern __shared__ float smem[];

    const int h   = blockIdx.x;   // 0..95
    const int b   = blockIdx.y;   // 0..3
    const int ixg = blockIdx.z;   // 0..2
    const int tid = threadIdx.x;

    const int q   = tid / 96;          // 0..6 : ix within group
    const int r0  = tid % 96;
    const int jh  = r0 / 48;           // tap half: j = 12*jh + jj
    const int r1  = r0 % 48;
    const int p   = r1 / 24;           // parity of w
    const int t   = r1 % 24;           // u-tile
    const int u0  = 4 * t;             // first parity-index owned
    const int ix     = ixg * 7 + q;
    const int h2base = h + 14 * ixg - 20;
    const int wb12   = u0 + 12 * jh;   // window base slot (float4-aligned)

    float acc[48];                     // [k 0..3][jj 0..11]
    #pragma unroll
    for (int i = 0; i < 48; i++) acc[i] = 0.0f;

    float2 v[NL];                      // register prefetch slots

    auto load_chunk = [&](int c0) {
        #pragma unroll
        for (int i = 0; i < NL; i++) {
            int idx = tid + i * NTHR;
            float2 val = make_float2(0.0f, 0.0f);
            if (idx < TOTAL_F2) {
                if (idx < CC * 96) {
                    int c = idx / 96;
                    int u = idx - c * 96;
                    val = *reinterpret_cast<const float2*>(
                        f1 + (((size_t)(b * 128 + c0 + c)) * 96 + h) * 192 + 2 * u);
                } else {
                    int t2 = idx - CC * 96;
                    int c  = t2 / 840;
                    int rr = t2 - c * 840;
                    int qq = rr / 120;
                    int s  = rr - qq * 120;
                    int h2 = h2base + 2 * qq;
                    int w0 = 2 * s - 20;
                    if (s < 116 && (unsigned)h2 < 96u && (unsigned)w0 < 192u)
                        val = *reinterpret_cast<const float2*>(
                            f2 + (((size_t)(b * 128 + c0 + c)) * 96 + h2) * 192 + w0);
                }
            }
            v[i] = val;
        }
    };

    auto store_chunk = [&](float* buf) {
        #pragma unroll
        for (int i = 0; i < NL; i++) {
            int idx = tid + i * NTHR;
            if (idx < TOTAL_F2) {
                if (idx < CC * 96) {
                    int c = idx / 96;
                    int u = idx - c * 96;
                    buf[(c * 2 + 0) * 96 + u] = v[i].x;   // even parity
                    buf[(c * 2 + 1) * 96 + u] = v[i].y;   // odd parity
                } else {
                    int t2 = idx - CC * 96;
                    int c  = t2 / 840;
                    int rr = t2 - c * 840;
                    int qq = rr / 120;
                    int s  = rr - qq * 120;
                    float* base = buf + S2OFF + ((c * 7 + qq) * 2) * 120 + s;
                    base[0]   = v[i].x;   // even parity
                    base[120] = v[i].y;   // odd parity
                }
            }
        }
    };

    // prologue
    load_chunk(0);
    store_chunk(smem);
    __syncthreads();

    const int NCHUNK = 128 / CC;   // 64
    #pragma unroll 1
    for (int cc = 0; cc < NCHUNK; cc++) {
        const float* cur = smem + (cc & 1) * BUF_FLOATS;
        float*       nxt = smem + ((cc + 1) & 1) * BUF_FLOATS;

        if (cc + 1 < NCHUNK) load_chunk((cc + 1) * CC);   // LDGs in flight

        #pragma unroll
        for (int c = 0; c < CC; c++) {
            float4 v1 = *reinterpret_cast<const float4*>(cur + (c * 2 + p) * 96 + u0);
            // slots needed: u0 + k + 12*jh + jj  ->  rel = k + jj in [0,14]
            const float4* wp = reinterpret_cast<const float4*>(
                cur + S2OFF + ((c * 7 + q) * 2 + p) * 120 + wb12);
            float4 W0 = wp[0], W1 = wp[1], W2 = wp[2], W3 = wp[3];
            float w[16] = {W0.x, W0.y, W0.z, W0.w, W1.x, W1.y, W1.z, W1.w,
                           W2.x, W2.y, W2.z, W2.w, W3.x, W3.y, W3.z, W3.w};
            float a[4] = {v1.x, v1.y, v1.z, v1.w};
            #pragma unroll
            for (int k = 0; k < 4; k++) {
                float fv = a[k];
                #pragma unroll
                for (int jj = 0; jj < 12; jj++)
                    acc[k * 12 + jj] = fmaf(fv, w[k + jj], acc[k * 12 + jj]);
            }
        }

        if (cc + 1 < NCHUNK) store_chunk(nxt);
        __syncthreads();
    }

    // store: j = 12*jh + jj; jh=0 stores jj 0..11, jh=1 stores jj 0..8 (j<=20)
    const int njj   = jh ? 9 : 12;
    const int wbase = 2 * u0 + p;
    size_t obase = (((size_t)b * 441 + (size_t)ix * 21 + 12 * jh) * 96 + h) * 192;
    #pragma unroll
    for (int jj = 0; jj < 12; jj++) {
        if (jj < njj) {
            size_t ob = obase + (size_t)jj * (96 * 192) + wbase;
            #pragma unroll
            for (int k = 0; k < 4; k++)
                out[ob + 2 * k] = acc[k * 12 + jj];
        }
    }
}

extern "C" void kernel_launch(void* const* d_in, const int* in_sizes, int n_in,
                              void* d_out, int out_size)
{
    const float* f1 = (const float*)d_in[0];
    const float* f2 = (const float*)d_in[1];
    float* out = (float*)d_out;

    size_t smem_bytes = (size_t)2 * BUF_FLOATS * sizeof(float);   // 29952 B
    cudaFuncSetAttribute(corr_kernel, cudaFuncAttributeMaxDynamicSharedMemorySize,
                         (int)smem_bytes);

    dim3 grid(96, 4, 3);   // (h, b, ix-group)
    corr_kernel<<<grid, NTHR, smem_bytes>>>(f1, f2, out);
}